// round 9
// baseline (speedup 1.0000x reference)
#include <cuda_runtime.h>
#include <cuda_fp16.h>
#include <cstdint>
#include <cstddef>

#define NB     4
#define NSEQ   4096
#define EDIM   128
#define FFD    512
#define NTOK   (NB * NSEQ)

// ---------------- scratch ----------------
__device__ float  g_h   [NTOK * EDIM];
__device__ float  g_S   [NTOK * EDIM];
__device__ __half g_Xh  [NTOK * 256];     // [t][256]: 2e=exp(k)*v, 2e+1=exp(k)
__device__ float  g_out1[NTOK * EDIM];
__device__ float  g_h2  [NTOK * EDIM];
__device__ float  g_t   [NTOK * FFD];

// ---------------- helpers ----------------
__device__ __forceinline__ float tf32r(float x) {
    uint32_t u;
    asm("cvt.rna.tf32.f32 %0, %1;" : "=r"(u) : "f"(x));
    return __uint_as_float(u);
}
__device__ __forceinline__ void mma_tf32(float* c, const float* a, const float* b) {
    asm volatile(
        "mma.sync.aligned.m16n8k8.row.col.f32.tf32.tf32.f32 "
        "{%0,%1,%2,%3}, {%4,%5,%6,%7}, {%8,%9}, {%0,%1,%2,%3};\n"
        : "+f"(c[0]), "+f"(c[1]), "+f"(c[2]), "+f"(c[3])
        : "r"(__float_as_uint(a[0])), "r"(__float_as_uint(a[1])),
          "r"(__float_as_uint(a[2])), "r"(__float_as_uint(a[3])),
          "r"(__float_as_uint(b[0])), "r"(__float_as_uint(b[1])));
}
__device__ __forceinline__ void mma_f16(float* c, const uint32_t* a, const uint32_t* b) {
    asm volatile(
        "mma.sync.aligned.m16n8k16.row.col.f32.f16.f16.f32 "
        "{%0,%1,%2,%3}, {%4,%5,%6,%7}, {%8,%9}, {%0,%1,%2,%3};\n"
        : "+f"(c[0]), "+f"(c[1]), "+f"(c[2]), "+f"(c[3])
        : "r"(a[0]), "r"(a[1]), "r"(a[2]), "r"(a[3]), "r"(b[0]), "r"(b[1]));
}
__device__ __forceinline__ void cp16(void* s, const void* gp) {
    uint32_t sa = (uint32_t)__cvta_generic_to_shared(s);
    asm volatile("cp.async.cg.shared.global [%0], [%1], 16;\n" :: "r"(sa), "l"(gp));
}
__device__ __forceinline__ void cp_commit() {
    asm volatile("cp.async.commit_group;\n" ::: "memory");
}
__device__ __forceinline__ void cp_wait0() {
    asm volatile("cp.async.wait_group 0;\n" ::: "memory");
}
__device__ __forceinline__ void cp_wait1() {
    asm volatile("cp.async.wait_group 1;\n" ::: "memory");
}
__device__ __forceinline__ void ldmx4(uint32_t& r0, uint32_t& r1, uint32_t& r2,
                                      uint32_t& r3, uint32_t addr) {
    asm volatile("ldmatrix.sync.aligned.m8n8.x4.shared.b16 {%0,%1,%2,%3}, [%4];"
                 : "=r"(r0), "=r"(r1), "=r"(r2), "=r"(r3) : "r"(addr));
}
__device__ __forceinline__ void ldmx4t(uint32_t& r0, uint32_t& r1, uint32_t& r2,
                                       uint32_t& r3, uint32_t addr) {
    asm volatile("ldmatrix.sync.aligned.m8n8.x4.trans.shared.b16 {%0,%1,%2,%3}, [%4];"
                 : "=r"(r0), "=r"(r1), "=r"(r2), "=r"(r3) : "r"(addr));
}
__device__ __forceinline__ uint32_t smem_u32(const void* p) {
    return (uint32_t)__cvta_generic_to_shared(p);
}

// ---------------- rmsnorm ----------------
__global__ void rmsnorm_kernel(const float* __restrict__ x,
                               const float* __restrict__ gw,
                               float* __restrict__ y) {
    int warp = (blockIdx.x * blockDim.x + threadIdx.x) >> 5;
    int lane = threadIdx.x & 31;
    if (warp >= NTOK) return;
    float4 v = reinterpret_cast<const float4*>(x + (size_t)warp * EDIM)[lane];
    float ss = v.x * v.x + v.y * v.y + v.z * v.z + v.w * v.w;
    #pragma unroll
    for (int o = 16; o > 0; o >>= 1) ss += __shfl_xor_sync(0xffffffffu, ss, o);
    float s = rsqrtf(ss * (1.0f / 128.0f) + 1e-6f);
    float4 g4 = reinterpret_cast<const float4*>(gw)[lane];
    float4 o4 = make_float4(v.x * s * g4.x, v.y * s * g4.y, v.z * s * g4.z, v.w * s * g4.w);
    reinterpret_cast<float4*>(y + (size_t)warp * EDIM)[lane] = o4;
}

// ---------------------------------------------------------------------------
// Fused QKV GEMM (cp.async double-buffered): block = 128 tokens x 32 cols of
// q,k,v. Epilogue: g_S = sigmoid(q); g_Xh = interleaved half pairs.
// ---------------------------------------------------------------------------
#define QK_A   4608
#define QK_B   1152
#define QK_BUF (QK_A + 3 * QK_B)
#define QKV_SMEM (2 * QK_BUF * 4)

__global__ __launch_bounds__(256)
void qkv_kernel(const float* __restrict__ h, const float* __restrict__ Wq,
                const float* __restrict__ Wk, const float* __restrict__ Wv) {
    extern __shared__ float smq[];
    const int m0 = blockIdx.x * 128;
    const int j0 = blockIdx.y * 32;
    const int tid = threadIdx.x, lane = tid & 31, warp = tid >> 5;
    const int wm = warp >> 1, wn = warp & 1;
    const int g = lane >> 2, tg = lane & 3;

    const float* Wp[3] = {Wq, Wk, Wv};

    auto cpTile = [&](int buf, int k0) {
        float* As = smq + buf * QK_BUF;
        #pragma unroll
        for (int i = 0; i < 4; i++) {
            int id = tid + i * 256;
            int m = id >> 3, c = (id & 7) << 2;
            cp16(As + m * 36 + c, h + (size_t)(m0 + m) * 128 + k0 + c);
        }
        int k = tid >> 3, c = (tid & 7) << 2;
        #pragma unroll
        for (int w = 0; w < 3; w++)
            cp16(As + QK_A + w * QK_B + k * 36 + c,
                 Wp[w] + (size_t)(k0 + k) * 128 + j0 + c);
    };

    float acc[3][2][2][4];
    #pragma unroll
    for (int w = 0; w < 3; w++)
        #pragma unroll
        for (int i = 0; i < 2; i++)
            #pragma unroll
            for (int j = 0; j < 2; j++)
                #pragma unroll
                for (int r = 0; r < 4; r++) acc[w][i][j][r] = 0.0f;

    cpTile(0, 0);
    cp_commit();

    for (int kt = 0; kt < 4; ++kt) {
        const int buf = kt & 1;
        if (kt + 1 < 4) { cpTile(buf ^ 1, (kt + 1) * 32); cp_commit(); cp_wait1(); }
        else            { cp_wait0(); }
        __syncthreads();
        const float* As = smq + buf * QK_BUF;
        const float* Bs = As + QK_A;
        #pragma unroll
        for (int ks = 0; ks < 4; ++ks) {
            const int kr = ks * 8 + tg;
            float a[2][4];
            #pragma unroll
            for (int mt = 0; mt < 2; ++mt) {
                int m = wm * 32 + mt * 16 + g;
                a[mt][0] = tf32r(As[m * 36 + kr]);
                a[mt][1] = tf32r(As[(m + 8) * 36 + kr]);
                a[mt][2] = tf32r(As[m * 36 + kr + 4]);
                a[mt][3] = tf32r(As[(m + 8) * 36 + kr + 4]);
            }
            #pragma unroll
            for (int w = 0; w < 3; w++) {
                #pragma unroll
                for (int nt = 0; nt < 2; ++nt) {
                    int n = wn * 16 + nt * 8 + g;
                    float bb[2];
                    bb[0] = tf32r(Bs[w * QK_B + kr * 36 + n]);
                    bb[1] = tf32r(Bs[w * QK_B + (kr + 4) * 36 + n]);
                    mma_tf32(acc[w][0][nt], a[0], bb);
                    mma_tf32(acc[w][1][nt], a[1], bb);
                }
            }
        }
        __syncthreads();
    }

    #pragma unroll
    for (int mt = 0; mt < 2; ++mt) {
        #pragma unroll
        for (int nt = 0; nt < 2; ++nt) {
            const int col = j0 + wn * 16 + nt * 8 + tg * 2;
            #pragma unroll
            for (int hh = 0; hh < 2; ++hh) {
                const int row = m0 + wm * 32 + mt * 16 + g + hh * 8;
                float q0 = acc[0][mt][nt][hh * 2], q1 = acc[0][mt][nt][hh * 2 + 1];
                float k0v = acc[1][mt][nt][hh * 2], k1v = acc[1][mt][nt][hh * 2 + 1];
                float v0 = acc[2][mt][nt][hh * 2], v1 = acc[2][mt][nt][hh * 2 + 1];
                float2 s2 = make_float2(1.0f / (1.0f + expf(-q0)),
                                        1.0f / (1.0f + expf(-q1)));
                *reinterpret_cast<float2*>(g_S + (size_t)row * 128 + col) = s2;
                float kw0 = expf(k0v), kw1 = expf(k1v);
                __half2 h0 = __floats2half2_rn(kw0 * v0, kw0);
                __half2 h1 = __floats2half2_rn(kw1 * v1, kw1);
                uint2 u;
                u.x = *reinterpret_cast<uint32_t*>(&h0);
                u.y = *reinterpret_cast<uint32_t*>(&h1);
                *reinterpret_cast<uint2*>(g_Xh + (size_t)row * 256 + 2 * col) = u;
            }
        }
    }
}

// ---------------------------------------------------------------------------
// Big GEMM (fp16 m16n8k16) + MEGA-FUSED epilogue:
//   att = sigmoid(q)*w1/w2  (kept in smem, fp16)
//   out1 = x + att @ Wo     (in-smem 128x128x128 fp16 GEMM)
//   h2   = rmsnorm(out1) * g_post
// ---------------------------------------------------------------------------
#define AH_STR 40
#define AH_BUF 5120
#define BH_STR 264
#define BH_BUF 8448
#define BH_OFF 10240
#define BIG_SMEM 71168
#define WM_STR 136              // epilogue tiles: [128][136] halfs

__global__ __launch_bounds__(512, 1)
void big_kernel(const float* __restrict__ dis, const float* __restrict__ alphap,
                const float* __restrict__ Wo, const float* __restrict__ x,
                const float* __restrict__ gpost) {
    extern __shared__ __half smh[];
    __half* Ah = smh;
    __half* Bh = smh + BH_OFF;
    const uint32_t smb = smem_u32(smh);
    __shared__ float rowss[128];

    const int tid = threadIdx.x, lane = tid & 31, warp = tid >> 5;
    const int wm = warp >> 2, wn = warp & 3;     // 4 x 4 warps
    const int g = lane >> 2, tg = lane & 3;
    const int b = blockIdx.y, j0 = blockIdx.x * 128;
    const float coef = 12.0f * alphap[0];
    const float* Ag = dis + (size_t)b * NSEQ * NSEQ;
    const __half* Xg = g_Xh + (size_t)b * NSEQ * 256;

    const int am = tid & 127, ar4 = (tid >> 7) << 2;

    const int lr = lane & 7, sel = lane >> 3;
    uint32_t aoff[2];
    #pragma unroll
    for (int mt = 0; mt < 2; ++mt)
        aoff[mt] = (uint32_t)((wm * 32 + mt * 16 + (sel & 1) * 8 + lr) * AH_STR +
                              (sel >> 1) * 8);
    const uint32_t lm_half = (uint32_t)((lane & 15) * BH_STR + wn * 64 + ((lane >> 4) << 3));

    float ra[2][4];
    float acc[2][8][4];
    #pragma unroll
    for (int i = 0; i < 2; i++)
        #pragma unroll
        for (int j = 0; j < 8; j++)
            #pragma unroll
            for (int r = 0; r < 4; r++) acc[i][j][r] = 0.0f;

    auto ldA = [&](int k0) {
        #pragma unroll
        for (int it = 0; it < 2; ++it) {
            const float* p = Ag + (size_t)(k0 + it * 16 + ar4) * NSEQ + j0 + am;
            ra[it][0] = p[0]; ra[it][1] = p[NSEQ];
            ra[it][2] = p[2 * NSEQ]; ra[it][3] = p[3 * NSEQ];
        }
    };
    auto stA = [&](int buf) {
        __half* base = Ah + buf * AH_BUF + am * AH_STR;
        #pragma unroll
        for (int it = 0; it < 2; ++it) {
            __half2 h01 = __floats2half2_rn(__expf(-coef * ra[it][0]),
                                            __expf(-coef * ra[it][1]));
            __half2 h23 = __floats2half2_rn(__expf(-coef * ra[it][2]),
                                            __expf(-coef * ra[it][3]));
            uint2 u;
            u.x = *reinterpret_cast<uint32_t*>(&h01);
            u.y = *reinterpret_cast<uint32_t*>(&h23);
            *reinterpret_cast<uint2*>(base + it * 16 + ar4) = u;
        }
    };
    auto cpB = [&](int stage, int k0) {
        #pragma unroll
        for (int it = 0; it < 2; ++it) {
            int ch = tid + it * 512;
            int row = ch >> 5, cc = (ch & 31) << 3;
            cp16(Bh + stage * BH_BUF + row * BH_STR + cc,
                 Xg + (size_t)(k0 + row) * 256 + cc);
        }
    };

    cpB(0, 0);  cp_commit();
    cpB(1, 32); cp_commit();
    ldA(0);
    stA(0);
    cp_wait1();
    __syncthreads();

    for (int kt = 0; kt < 128; ++kt) {
        const int sbuf = kt % 3;
        const int abuf = kt & 1;
        if (kt + 2 < 128) { cpB((kt + 2) % 3, (kt + 2) * 32); cp_commit(); }
        if (kt + 1 < 128) ldA((kt + 1) * 32);

        const uint32_t abase = smb + 2u * (abuf * AH_BUF);
        const uint32_t bbase = smb + 2u * (BH_OFF + sbuf * BH_BUF + lm_half);
        #pragma unroll
        for (int ks = 0; ks < 2; ++ks) {
            const int kb = ks * 16;
            uint32_t a[2][4];
            #pragma unroll
            for (int mt = 0; mt < 2; ++mt)
                ldmx4(a[mt][0], a[mt][1], a[mt][2], a[mt][3],
                      abase + 2u * (aoff[mt] + kb));
            #pragma unroll
            for (int np = 0; np < 4; ++np) {
                uint32_t r0, r1, r2, r3;
                ldmx4t(r0, r1, r2, r3, bbase + 2u * (kb * BH_STR + np * 16));
                uint32_t b0[2] = {r0, r1}, b1[2] = {r2, r3};
                mma_f16(acc[0][np * 2],     a[0], b0);
                mma_f16(acc[1][np * 2],     a[1], b0);
                mma_f16(acc[0][np * 2 + 1], a[0], b1);
                mma_f16(acc[1][np * 2 + 1], a[1], b1);
            }
        }
        if (kt + 1 < 128) stA(abuf ^ 1);
        cp_wait1();
        __syncthreads();
    }

    // ======================= fused epilogue =======================
    __half* Aatt = smh;            // [128][136] att fp16
    __half* Wos  = smh + 128 * WM_STR;  // [128][136] Wo fp16 (k=e major)
    if (tid < 128) rowss[tid] = 0.0f;

    const size_t rowbase = (size_t)b * NSEQ + j0;

    // stage Wo (f32 -> f16), [e][c] rows
    #pragma unroll
    for (int it = 0; it < 8; ++it) {
        int idx = tid + it * 512;          // 4096 float4
        int e = idx >> 5, c4 = (idx & 31) << 2;
        float4 w = *reinterpret_cast<const float4*>(Wo + (size_t)e * 128 + c4);
        __half2 w01 = __floats2half2_rn(w.x, w.y);
        __half2 w23 = __floats2half2_rn(w.z, w.w);
        uint2 u;
        u.x = *reinterpret_cast<uint32_t*>(&w01);
        u.y = *reinterpret_cast<uint32_t*>(&w23);
        *reinterpret_cast<uint2*>(Wos + e * WM_STR + c4) = u;
    }

    // att = S * w1/w2 -> smem fp16
    #pragma unroll
    for (int mt = 0; mt < 2; ++mt) {
        const int r0 = wm * 32 + mt * 16 + g;
        #pragma unroll
        for (int nt = 0; nt < 8; ++nt) {
            const int e = wn * 32 + nt * 4 + tg;
            const size_t i0 = (rowbase + r0) * 128 + e;
            const size_t i1 = (rowbase + r0 + 8) * 128 + e;
            float a0 = g_S[i0] * __fdividef(acc[mt][nt][0], acc[mt][nt][1]);
            float a1 = g_S[i1] * __fdividef(acc[mt][nt][2], acc[mt][nt][3]);
            Aatt[r0 * WM_STR + e]       = __float2half(a0);
            Aatt[(r0 + 8) * WM_STR + e] = __float2half(a1);
        }
    }
    __syncthreads();

    // in-smem GEMM: out1acc[m][c] = sum_e att[m][e] * Wo[e][c]
    float acc2[2][4][4];
    #pragma unroll
    for (int i = 0; i < 2; i++)
        #pragma unroll
        for (int j = 0; j < 4; j++)
            #pragma unroll
            for (int r = 0; r < 4; r++) acc2[i][j][r] = 0.0f;

    uint32_t aoff2[2];
    #pragma unroll
    for (int mt = 0; mt < 2; ++mt)
        aoff2[mt] = (uint32_t)((wm * 32 + mt * 16 + (sel & 1) * 8 + lr) * WM_STR +
                               (sel >> 1) * 8);
    const uint32_t lmw = (uint32_t)((lane & 15) * WM_STR + wn * 32 + ((lane >> 4) << 3));
    const uint32_t wos_base = smb + 2u * (128 * WM_STR);

    #pragma unroll
    for (int kk = 0; kk < 128; kk += 16) {
        uint32_t a2[2][4];
        #pragma unroll
        for (int mt = 0; mt < 2; ++mt)
            ldmx4(a2[mt][0], a2[mt][1], a2[mt][2], a2[mt][3],
                  smb + 2u * (aoff2[mt] + kk));
        #pragma unroll
        for (int np = 0; np < 2; ++np) {
            uint32_t r0, r1, r2, r3;
            ldmx4t(r0, r1, r2, r3, wos_base + 2u * (lmw + kk * WM_STR + np * 16));
            uint32_t b0[2] = {r0, r1}, b1[2] = {r2, r3};
            mma_f16(acc2[0][np * 2],     a2[0], b0);
            mma_f16(acc2[1][np * 2],     a2[1], b0);
            mma_f16(acc2[0][np * 2 + 1], a2[0], b1);
            mma_f16(acc2[1][np * 2 + 1], a2[1], b1);
        }
    }

    // out1 = x + attWo; accumulate row sum-of-squares
    #pragma unroll
    for (int mt = 0; mt < 2; ++mt) {
        #pragma unroll
        for (int h = 0; h < 2; ++h) {
            const int rl = wm * 32 + mt * 16 + g + h * 8;
            const size_t rowg = rowbase + rl;
            float ss = 0.0f;
            #pragma unroll
            for (int nt = 0; nt < 4; ++nt) {
                const int c = wn * 32 + nt * 8 + tg * 2;
                float2 xv = *reinterpret_cast<const float2*>(x + rowg * 128 + c);
                float v0 = acc2[mt][nt][h * 2 + 0] + xv.x;
                float v1 = acc2[mt][nt][h * 2 + 1] + xv.y;
                acc2[mt][nt][h * 2 + 0] = v0;
                acc2[mt][nt][h * 2 + 1] = v1;
                float2 o = make_float2(v0, v1);
                *reinterpret_cast<float2*>(g_out1 + rowg * 128 + c) = o;
                ss += v0 * v0 + v1 * v1;
            }
            ss += __shfl_xor_sync(0xffffffffu, ss, 1);
            ss += __shfl_xor_sync(0xffffffffu, ss, 2);
            if (tg == 0) atomicAdd(&rowss[rl], ss);
        }
    }
    __syncthreads();

    // h2 = out1 * rsqrt(mean+eps) * g_post
    #pragma unroll
    for (int mt = 0; mt < 2; ++mt) {
        #pragma unroll
        for (int h = 0; h < 2; ++h) {
            const int rl = wm * 32 + mt * 16 + g + h * 8;
            const size_t rowg = rowbase + rl;
            const float sc = rsqrtf(rowss[rl] * (1.0f / 128.0f) + 1e-6f);
            #pragma unroll
            for (int nt = 0; nt < 4; ++nt) {
                const int c = wn * 32 + nt * 8 + tg * 2;
                float2 gp = *reinterpret_cast<const float2*>(gpost + c);
                float2 o;
                o.x = acc2[mt][nt][h * 2 + 0] * sc * gp.x;
                o.y = acc2[mt][nt][h * 2 + 1] * sc * gp.y;
                *reinterpret_cast<float2*>(g_h2 + rowg * 128 + c) = o;
            }
        }
    }
}

// ---------------------------------------------------------------------------
// Small GEMM (tf32, cp.async double-buffered): BM=128, BN=64, 256 threads.
// mode 2: relu(+bias)   3: +bias+res
// ---------------------------------------------------------------------------
#define SG_A   4608
#define SG_B   2304
#define SG_BUF (SG_A + SG_B)
#define SG_SMEM (2 * SG_BUF * 4)

__global__ __launch_bounds__(256)
void gemm_small_kernel(const float* __restrict__ A, const float* __restrict__ B,
                       float* __restrict__ C, int K, int N, int mode,
                       const float* __restrict__ bias, const float* __restrict__ res) {
    extern __shared__ float smg[];
    const int m0 = blockIdx.x * 128;
    const int n0 = blockIdx.y * 64;
    const int tid = threadIdx.x, lane = tid & 31, warp = tid >> 5;
    const int wm = warp >> 1, wn = warp & 1;
    const int g = lane >> 2, tg = lane & 3;

    auto cpTile = [&](int buf, int k0) {
        float* As = smg + buf * SG_BUF;
        float* Bs = As + SG_A;
        #pragma unroll
        for (int i = 0; i < 4; i++) {
            int id = tid + i * 256;
            int m = id >> 3, c = (id & 7) << 2;
            cp16(As + m * 36 + c, A + (size_t)(m0 + m) * K + k0 + c);
        }
        #pragma unroll
        for (int i = 0; i < 2; i++) {
            int id = tid + i * 256;
            int k = id >> 4, c = (id & 15) << 2;
            cp16(Bs + k * 72 + c, B + (size_t)(k0 + k) * N + n0 + c);
        }
    };

    float acc[2][4][4];
    #pragma unroll
    for (int i = 0; i < 2; i++)
        #pragma unroll
        for (int j = 0; j < 4; j++)
            #pragma unroll
            for (int r = 0; r < 4; r++) acc[i][j][r] = 0.0f;

    const int KT = K / 32;
    cpTile(0, 0);
    cp_commit();

    for (int kt = 0; kt < KT; ++kt) {
        const int buf = kt & 1;
        if (kt + 1 < KT) { cpTile(buf ^ 1, (kt + 1) * 32); cp_commit(); cp_wait1(); }
        else             { cp_wait0(); }
        __syncthreads();
        const float* As = smg + buf * SG_BUF;
        const float* Bs = As + SG_A;
        #pragma unroll
        for (int ks = 0; ks < 4; ++ks) {
            const int kr = ks * 8 + tg;
            float a[2][4];
            #pragma unroll
            for (int mt = 0; mt < 2; ++mt) {
                int m = wm * 32 + mt * 16 + g;
                a[mt][0] = tf32r(As[m * 36 + kr]);
                a[mt][1] = tf32r(As[(m + 8) * 36 + kr]);
                a[mt][2] = tf32r(As[m * 36 + kr + 4]);
                a[mt][3] = tf32r(As[(m + 8) * 36 + kr + 4]);
            }
            float bb[4][2];
            #pragma unroll
            for (int nt = 0; nt < 4; ++nt) {
                int n = wn * 32 + nt * 8 + g;
                bb[nt][0] = tf32r(Bs[kr * 72 + n]);
                bb[nt][1] = tf32r(Bs[(kr + 4) * 72 + n]);
            }
            #pragma unroll
            for (int mt = 0; mt < 2; ++mt)
                #pragma unroll
                for (int nt = 0; nt < 4; ++nt)
                    mma_tf32(acc[mt][nt], a[mt], bb[nt]);
        }
        __syncthreads();
    }

    #pragma unroll
    for (int mt = 0; mt < 2; ++mt) {
        const int row0 = m0 + wm * 32 + mt * 16 + g;
        #pragma unroll
        for (int nt = 0; nt < 4; ++nt) {
            const int col = n0 + wn * 32 + nt * 8 + tg * 2;
            #pragma unroll
            for (int h = 0; h < 2; ++h) {
                const int row = row0 + h * 8;
                float v0 = acc[mt][nt][h * 2 + 0];
                float v1 = acc[mt][nt][h * 2 + 1];
                if (mode == 2) {
                    v0 = fmaxf(v0 + bias[col], 0.0f);
                    v1 = fmaxf(v1 + bias[col + 1], 0.0f);
                } else {
                    v0 += bias[col]     + res[(size_t)row * N + col];
                    v1 += bias[col + 1] + res[(size_t)row * N + col + 1];
                }
                C[(size_t)row * N + col]     = v0;
                C[(size_t)row * N + col + 1] = v1;
            }
        }
    }
}

// ---------------- launch ----------------
extern "C" void kernel_launch(void* const* d_in, const int* in_sizes, int n_in,
                              void* d_out, int out_size) {
    const float* x     = (const float*)d_in[0];
    const float* dis   = (const float*)d_in[1];
    const float* g_in  = (const float*)d_in[2];
    const float* g_po  = (const float*)d_in[3];
    const float* Wq    = (const float*)d_in[4];
    const float* Wk    = (const float*)d_in[5];
    const float* Wv    = (const float*)d_in[6];
    const float* alpha = (const float*)d_in[7];
    const float* Wo    = (const float*)d_in[8];
    const float* W1    = (const float*)d_in[9];
    const float* b1    = (const float*)d_in[10];
    const float* W2    = (const float*)d_in[11];
    const float* b2    = (const float*)d_in[12];
    float* out = (float*)d_out;

    float *p_h, *p_out1, *p_h2, *p_t;
    cudaGetSymbolAddress((void**)&p_h,    g_h);
    cudaGetSymbolAddress((void**)&p_out1, g_out1);
    cudaGetSymbolAddress((void**)&p_h2,   g_h2);
    cudaGetSymbolAddress((void**)&p_t,    g_t);

    cudaFuncSetAttribute(big_kernel,
                         cudaFuncAttributeMaxDynamicSharedMemorySize, BIG_SMEM);
    cudaFuncSetAttribute(qkv_kernel,
                         cudaFuncAttributeMaxDynamicSharedMemorySize, QKV_SMEM);
    cudaFuncSetAttribute(gemm_small_kernel,
                         cudaFuncAttributeMaxDynamicSharedMemorySize, SG_SMEM);

    rmsnorm_kernel<<<NTOK / 8, 256>>>(x, g_in, p_h);
    qkv_kernel<<<dim3(NTOK / 128, 4), 256, QKV_SMEM>>>(p_h, Wq, Wk, Wv);
    // big GEMM + att + Wo + residual + rmsnorm2 (all fused)
    big_kernel<<<dim3(NSEQ / 128, NB), 512, BIG_SMEM>>>(dis, alpha, Wo, x, g_po);
    // t = relu(h2 @ W1 + b1)
    gemm_small_kernel<<<dim3(NTOK / 128, 8), 256, SG_SMEM>>>(p_h2, W1, p_t,
                                                    128, 512, 2, b1, nullptr);
    // out = out1 + t @ W2 + b2
    gemm_small_kernel<<<dim3(NTOK / 128, 2), 256, SG_SMEM>>>(p_t, W2, out,
                                                    512, 128, 3, b2, p_out1);
}

// round 10
// speedup vs baseline: 1.4153x; 1.4153x over previous
#include <cuda_runtime.h>
#include <cuda_fp16.h>
#include <cstdint>
#include <cstddef>

#define NB     4
#define NSEQ   4096
#define EDIM   128
#define FFD    512
#define NTOK   (NB * NSEQ)

// ---------------- scratch ----------------
__device__ float  g_h   [NTOK * EDIM];
__device__ float  g_S   [NTOK * EDIM];
__device__ __half g_Xh  [NTOK * 256];
__device__ float  g_att [NTOK * EDIM];
__device__ float  g_out1[NTOK * EDIM];
__device__ __half g_h2h [NTOK * EDIM];
__device__ __half g_th  [NTOK * FFD];
__device__ __half g_W1h [EDIM * FFD];
__device__ __half g_W2h [FFD * EDIM];

// ---------------- helpers ----------------
__device__ __forceinline__ float tf32r(float x) {
    uint32_t u;
    asm("cvt.rna.tf32.f32 %0, %1;" : "=r"(u) : "f"(x));
    return __uint_as_float(u);
}
__device__ __forceinline__ void mma_tf32(float* c, const float* a, const float* b) {
    asm volatile(
        "mma.sync.aligned.m16n8k8.row.col.f32.tf32.tf32.f32 "
        "{%0,%1,%2,%3}, {%4,%5,%6,%7}, {%8,%9}, {%0,%1,%2,%3};\n"
        : "+f"(c[0]), "+f"(c[1]), "+f"(c[2]), "+f"(c[3])
        : "r"(__float_as_uint(a[0])), "r"(__float_as_uint(a[1])),
          "r"(__float_as_uint(a[2])), "r"(__float_as_uint(a[3])),
          "r"(__float_as_uint(b[0])), "r"(__float_as_uint(b[1])));
}
__device__ __forceinline__ void mma_f16(float* c, const uint32_t* a, const uint32_t* b) {
    asm volatile(
        "mma.sync.aligned.m16n8k16.row.col.f32.f16.f16.f32 "
        "{%0,%1,%2,%3}, {%4,%5,%6,%7}, {%8,%9}, {%0,%1,%2,%3};\n"
        : "+f"(c[0]), "+f"(c[1]), "+f"(c[2]), "+f"(c[3])
        : "r"(a[0]), "r"(a[1]), "r"(a[2]), "r"(a[3]), "r"(b[0]), "r"(b[1]));
}
__device__ __forceinline__ void cp16(void* s, const void* gp) {
    uint32_t sa = (uint32_t)__cvta_generic_to_shared(s);
    asm volatile("cp.async.cg.shared.global [%0], [%1], 16;\n" :: "r"(sa), "l"(gp));
}
__device__ __forceinline__ void cp_commit() {
    asm volatile("cp.async.commit_group;\n" ::: "memory");
}
__device__ __forceinline__ void cp_wait0() {
    asm volatile("cp.async.wait_group 0;\n" ::: "memory");
}
__device__ __forceinline__ void cp_wait1() {
    asm volatile("cp.async.wait_group 1;\n" ::: "memory");
}
__device__ __forceinline__ void ldmx4(uint32_t& r0, uint32_t& r1, uint32_t& r2,
                                      uint32_t& r3, uint32_t addr) {
    asm volatile("ldmatrix.sync.aligned.m8n8.x4.shared.b16 {%0,%1,%2,%3}, [%4];"
                 : "=r"(r0), "=r"(r1), "=r"(r2), "=r"(r3) : "r"(addr));
}
__device__ __forceinline__ void ldmx4t(uint32_t& r0, uint32_t& r1, uint32_t& r2,
                                       uint32_t& r3, uint32_t addr) {
    asm volatile("ldmatrix.sync.aligned.m8n8.x4.trans.shared.b16 {%0,%1,%2,%3}, [%4];"
                 : "=r"(r0), "=r"(r1), "=r"(r2), "=r"(r3) : "r"(addr));
}
__device__ __forceinline__ uint32_t smem_u32(const void* p) {
    return (uint32_t)__cvta_generic_to_shared(p);
}

// ---------------- pack W1/W2 to half ----------------
__global__ void pack_w_kernel(const float* __restrict__ W1,
                              const float* __restrict__ W2) {
    int i = blockIdx.x * blockDim.x + threadIdx.x;
    if (i < EDIM * FFD) {
        g_W1h[i] = __float2half(W1[i]);
        g_W2h[i] = __float2half(W2[i]);
    }
}

// ---------------- rmsnorm (f32 out) ----------------
__global__ void rmsnorm_kernel(const float* __restrict__ x,
                               const float* __restrict__ gw,
                               float* __restrict__ y) {
    int warp = (blockIdx.x * blockDim.x + threadIdx.x) >> 5;
    int lane = threadIdx.x & 31;
    if (warp >= NTOK) return;
    float4 v = reinterpret_cast<const float4*>(x + (size_t)warp * EDIM)[lane];
    float ss = v.x * v.x + v.y * v.y + v.z * v.z + v.w * v.w;
    #pragma unroll
    for (int o = 16; o > 0; o >>= 1) ss += __shfl_xor_sync(0xffffffffu, ss, o);
    float s = rsqrtf(ss * (1.0f / 128.0f) + 1e-6f);
    float4 g4 = reinterpret_cast<const float4*>(gw)[lane];
    float4 o4 = make_float4(v.x * s * g4.x, v.y * s * g4.y, v.z * s * g4.z, v.w * s * g4.w);
    reinterpret_cast<float4*>(y + (size_t)warp * EDIM)[lane] = o4;
}

// ---------------- rmsnorm (half out) ----------------
__global__ void rmsnorm_h_kernel(const float* __restrict__ x,
                                 const float* __restrict__ gw,
                                 __half* __restrict__ y) {
    int warp = (blockIdx.x * blockDim.x + threadIdx.x) >> 5;
    int lane = threadIdx.x & 31;
    if (warp >= NTOK) return;
    float4 v = reinterpret_cast<const float4*>(x + (size_t)warp * EDIM)[lane];
    float ss = v.x * v.x + v.y * v.y + v.z * v.z + v.w * v.w;
    #pragma unroll
    for (int o = 16; o > 0; o >>= 1) ss += __shfl_xor_sync(0xffffffffu, ss, o);
    float s = rsqrtf(ss * (1.0f / 128.0f) + 1e-6f);
    float4 g4 = reinterpret_cast<const float4*>(gw)[lane];
    __half2 h0 = __floats2half2_rn(v.x * s * g4.x, v.y * s * g4.y);
    __half2 h1 = __floats2half2_rn(v.z * s * g4.z, v.w * s * g4.w);
    uint2 u;
    u.x = *reinterpret_cast<uint32_t*>(&h0);
    u.y = *reinterpret_cast<uint32_t*>(&h1);
    *reinterpret_cast<uint2*>(y + (size_t)warp * EDIM + lane * 4) = u;
}

// ---------------------------------------------------------------------------
// Fused QKV GEMM (cp.async double-buffered) — unchanged from R8
// ---------------------------------------------------------------------------
#define QK_A   4608
#define QK_B   1152
#define QK_BUF (QK_A + 3 * QK_B)
#define QKV_SMEM (2 * QK_BUF * 4)

__global__ __launch_bounds__(256)
void qkv_kernel(const float* __restrict__ h, const float* __restrict__ Wq,
                const float* __restrict__ Wk, const float* __restrict__ Wv) {
    extern __shared__ float smq[];
    const int m0 = blockIdx.x * 128;
    const int j0 = blockIdx.y * 32;
    const int tid = threadIdx.x, lane = tid & 31, warp = tid >> 5;
    const int wm = warp >> 1, wn = warp & 1;
    const int g = lane >> 2, tg = lane & 3;

    const float* Wp[3] = {Wq, Wk, Wv};

    auto cpTile = [&](int buf, int k0) {
        float* As = smq + buf * QK_BUF;
        #pragma unroll
        for (int i = 0; i < 4; i++) {
            int id = tid + i * 256;
            int m = id >> 3, c = (id & 7) << 2;
            cp16(As + m * 36 + c, h + (size_t)(m0 + m) * 128 + k0 + c);
        }
        int k = tid >> 3, c = (tid & 7) << 2;
        #pragma unroll
        for (int w = 0; w < 3; w++)
            cp16(As + QK_A + w * QK_B + k * 36 + c,
                 Wp[w] + (size_t)(k0 + k) * 128 + j0 + c);
    };

    float acc[3][2][2][4];
    #pragma unroll
    for (int w = 0; w < 3; w++)
        #pragma unroll
        for (int i = 0; i < 2; i++)
            #pragma unroll
            for (int j = 0; j < 2; j++)
                #pragma unroll
                for (int r = 0; r < 4; r++) acc[w][i][j][r] = 0.0f;

    cpTile(0, 0);
    cp_commit();

    for (int kt = 0; kt < 4; ++kt) {
        const int buf = kt & 1;
        if (kt + 1 < 4) { cpTile(buf ^ 1, (kt + 1) * 32); cp_commit(); cp_wait1(); }
        else            { cp_wait0(); }
        __syncthreads();
        const float* As = smq + buf * QK_BUF;
        const float* Bs = As + QK_A;
        #pragma unroll
        for (int ks = 0; ks < 4; ++ks) {
            const int kr = ks * 8 + tg;
            float a[2][4];
            #pragma unroll
            for (int mt = 0; mt < 2; ++mt) {
                int m = wm * 32 + mt * 16 + g;
                a[mt][0] = tf32r(As[m * 36 + kr]);
                a[mt][1] = tf32r(As[(m + 8) * 36 + kr]);
                a[mt][2] = tf32r(As[m * 36 + kr + 4]);
                a[mt][3] = tf32r(As[(m + 8) * 36 + kr + 4]);
            }
            #pragma unroll
            for (int w = 0; w < 3; w++) {
                #pragma unroll
                for (int nt = 0; nt < 2; ++nt) {
                    int n = wn * 16 + nt * 8 + g;
                    float bb[2];
                    bb[0] = tf32r(Bs[w * QK_B + kr * 36 + n]);
                    bb[1] = tf32r(Bs[w * QK_B + (kr + 4) * 36 + n]);
                    mma_tf32(acc[w][0][nt], a[0], bb);
                    mma_tf32(acc[w][1][nt], a[1], bb);
                }
            }
        }
        __syncthreads();
    }

    #pragma unroll
    for (int mt = 0; mt < 2; ++mt) {
        #pragma unroll
        for (int nt = 0; nt < 2; ++nt) {
            const int col = j0 + wn * 16 + nt * 8 + tg * 2;
            #pragma unroll
            for (int hh = 0; hh < 2; ++hh) {
                const int row = m0 + wm * 32 + mt * 16 + g + hh * 8;
                float q0 = acc[0][mt][nt][hh * 2], q1 = acc[0][mt][nt][hh * 2 + 1];
                float k0v = acc[1][mt][nt][hh * 2], k1v = acc[1][mt][nt][hh * 2 + 1];
                float v0 = acc[2][mt][nt][hh * 2], v1 = acc[2][mt][nt][hh * 2 + 1];
                float2 s2 = make_float2(1.0f / (1.0f + expf(-q0)),
                                        1.0f / (1.0f + expf(-q1)));
                *reinterpret_cast<float2*>(g_S + (size_t)row * 128 + col) = s2;
                float kw0 = expf(k0v), kw1 = expf(k1v);
                __half2 h0 = __floats2half2_rn(kw0 * v0, kw0);
                __half2 h1 = __floats2half2_rn(kw1 * v1, kw1);
                uint2 u;
                u.x = *reinterpret_cast<uint32_t*>(&h0);
                u.y = *reinterpret_cast<uint32_t*>(&h1);
                *reinterpret_cast<uint2*>(g_Xh + (size_t)row * 256 + 2 * col) = u;
            }
        }
    }
}

// ---------------------------------------------------------------------------
// Big GEMM (fp16 m16n8k16) — unchanged from R8 (att epilogue only)
// ---------------------------------------------------------------------------
#define AH_STR 40
#define AH_BUF 5120
#define BH_STR 264
#define BH_BUF 8448
#define BH_OFF 10240
#define BIG_SMEM 71168

__global__ __launch_bounds__(512, 1)
void big_kernel(const float* __restrict__ dis, const float* __restrict__ alphap) {
    extern __shared__ __half smh[];
    __half* Ah = smh;
    __half* Bh = smh + BH_OFF;
    const uint32_t smb = smem_u32(smh);

    const int tid = threadIdx.x, lane = tid & 31, warp = tid >> 5;
    const int wm = warp >> 2, wn = warp & 3;
    const int g = lane >> 2, tg = lane & 3;
    const int b = blockIdx.y, j0 = blockIdx.x * 128;
    const float coef = 12.0f * alphap[0];
    const float* Ag = dis + (size_t)b * NSEQ * NSEQ;
    const __half* Xg = g_Xh + (size_t)b * NSEQ * 256;

    const int am = tid & 127, ar4 = (tid >> 7) << 2;

    const int lr = lane & 7, sel = lane >> 3;
    uint32_t aoff[2];
    #pragma unroll
    for (int mt = 0; mt < 2; ++mt)
        aoff[mt] = (uint32_t)((wm * 32 + mt * 16 + (sel & 1) * 8 + lr) * AH_STR +
                              (sel >> 1) * 8);
    const uint32_t lm_half = (uint32_t)((lane & 15) * BH_STR + wn * 64 + ((lane >> 4) << 3));

    float ra[2][4];
    float acc[2][8][4];
    #pragma unroll
    for (int i = 0; i < 2; i++)
        #pragma unroll
        for (int j = 0; j < 8; j++)
            #pragma unroll
            for (int r = 0; r < 4; r++) acc[i][j][r] = 0.0f;

    auto ldA = [&](int k0) {
        #pragma unroll
        for (int it = 0; it < 2; ++it) {
            const float* p = Ag + (size_t)(k0 + it * 16 + ar4) * NSEQ + j0 + am;
            ra[it][0] = p[0]; ra[it][1] = p[NSEQ];
            ra[it][2] = p[2 * NSEQ]; ra[it][3] = p[3 * NSEQ];
        }
    };
    auto stA = [&](int buf) {
        __half* base = Ah + buf * AH_BUF + am * AH_STR;
        #pragma unroll
        for (int it = 0; it < 2; ++it) {
            __half2 h01 = __floats2half2_rn(__expf(-coef * ra[it][0]),
                                            __expf(-coef * ra[it][1]));
            __half2 h23 = __floats2half2_rn(__expf(-coef * ra[it][2]),
                                            __expf(-coef * ra[it][3]));
            uint2 u;
            u.x = *reinterpret_cast<uint32_t*>(&h01);
            u.y = *reinterpret_cast<uint32_t*>(&h23);
            *reinterpret_cast<uint2*>(base + it * 16 + ar4) = u;
        }
    };
    auto cpB = [&](int stage, int k0) {
        #pragma unroll
        for (int it = 0; it < 2; ++it) {
            int ch = tid + it * 512;
            int row = ch >> 5, cc = (ch & 31) << 3;
            cp16(Bh + stage * BH_BUF + row * BH_STR + cc,
                 Xg + (size_t)(k0 + row) * 256 + cc);
        }
    };

    cpB(0, 0);  cp_commit();
    cpB(1, 32); cp_commit();
    ldA(0);
    stA(0);
    cp_wait1();
    __syncthreads();

    for (int kt = 0; kt < 128; ++kt) {
        const int sbuf = kt % 3;
        const int abuf = kt & 1;
        if (kt + 2 < 128) { cpB((kt + 2) % 3, (kt + 2) * 32); cp_commit(); }
        if (kt + 1 < 128) ldA((kt + 1) * 32);

        const uint32_t abase = smb + 2u * (abuf * AH_BUF);
        const uint32_t bbase = smb + 2u * (BH_OFF + sbuf * BH_BUF + lm_half);
        #pragma unroll
        for (int ks = 0; ks < 2; ++ks) {
            const int kb = ks * 16;
            uint32_t a[2][4];
            #pragma unroll
            for (int mt = 0; mt < 2; ++mt)
                ldmx4(a[mt][0], a[mt][1], a[mt][2], a[mt][3],
                      abase + 2u * (aoff[mt] + kb));
            #pragma unroll
            for (int np = 0; np < 4; ++np) {
                uint32_t r0, r1, r2, r3;
                ldmx4t(r0, r1, r2, r3, bbase + 2u * (kb * BH_STR + np * 16));
                uint32_t b0[2] = {r0, r1}, b1[2] = {r2, r3};
                mma_f16(acc[0][np * 2],     a[0], b0);
                mma_f16(acc[1][np * 2],     a[1], b0);
                mma_f16(acc[0][np * 2 + 1], a[0], b1);
                mma_f16(acc[1][np * 2 + 1], a[1], b1);
            }
        }
        if (kt + 1 < 128) stA(abuf ^ 1);
        cp_wait1();
        __syncthreads();
    }

    const size_t rowbase = (size_t)b * NSEQ + j0;
    #pragma unroll
    for (int mt = 0; mt < 2; ++mt) {
        const int r0 = wm * 32 + mt * 16 + g;
        #pragma unroll
        for (int nt = 0; nt < 8; ++nt) {
            const int e = wn * 32 + nt * 4 + tg;
            const size_t i0 = (rowbase + r0) * 128 + e;
            const size_t i1 = (rowbase + r0 + 8) * 128 + e;
            g_att[i0] = g_S[i0] * __fdividef(acc[mt][nt][0], acc[mt][nt][1]);
            g_att[i1] = g_S[i1] * __fdividef(acc[mt][nt][2], acc[mt][nt][3]);
        }
    }
}

// ---------------------------------------------------------------------------
// Wo GEMM (tf32, cp.async double-buffered) — R8 gemm_small, mode fixed: +res
// ---------------------------------------------------------------------------
#define SG_A   4608
#define SG_B   2304
#define SG_BUF (SG_A + SG_B)
#define SG_SMEM (2 * SG_BUF * 4)

__global__ __launch_bounds__(256)
void wo_kernel(const float* __restrict__ A, const float* __restrict__ B,
               float* __restrict__ C, const float* __restrict__ res) {
    extern __shared__ float smg[];
    const int m0 = blockIdx.x * 128;
    const int n0 = blockIdx.y * 64;
    const int tid = threadIdx.x, lane = tid & 31, warp = tid >> 5;
    const int wm = warp >> 1, wn = warp & 1;
    const int g = lane >> 2, tg = lane & 3;
    const int K = 128, N = 128;

    auto cpTile = [&](int buf, int k0) {
        float* As = smg + buf * SG_BUF;
        float* Bs = As + SG_A;
        #pragma unroll
        for (int i = 0; i < 4; i++) {
            int id = tid + i * 256;
            int m = id >> 3, c = (id & 7) << 2;
            cp16(As + m * 36 + c, A + (size_t)(m0 + m) * K + k0 + c);
        }
        #pragma unroll
        for (int i = 0; i < 2; i++) {
            int id = tid + i * 256;
            int k = id >> 4, c = (id & 15) << 2;
            cp16(Bs + k * 72 + c, B + (size_t)(k0 + k) * N + n0 + c);
        }
    };

    float acc[2][4][4];
    #pragma unroll
    for (int i = 0; i < 2; i++)
        #pragma unroll
        for (int j = 0; j < 4; j++)
            #pragma unroll
            for (int r = 0; r < 4; r++) acc[i][j][r] = 0.0f;

    cpTile(0, 0);
    cp_commit();

    for (int kt = 0; kt < 4; ++kt) {
        const int buf = kt & 1;
        if (kt + 1 < 4) { cpTile(buf ^ 1, (kt + 1) * 32); cp_commit(); cp_wait1(); }
        else            { cp_wait0(); }
        __syncthreads();
        const float* As = smg + buf * SG_BUF;
        const float* Bs = As + SG_A;
        #pragma unroll
        for (int ks = 0; ks < 4; ++ks) {
            const int kr = ks * 8 + tg;
            float a[2][4];
            #pragma unroll
            for (int mt = 0; mt < 2; ++mt) {
                int m = wm * 32 + mt * 16 + g;
                a[mt][0] = tf32r(As[m * 36 + kr]);
                a[mt][1] = tf32r(As[(m + 8) * 36 + kr]);
                a[mt][2] = tf32r(As[m * 36 + kr + 4]);
                a[mt][3] = tf32r(As[(m + 8) * 36 + kr + 4]);
            }
            float bb[4][2];
            #pragma unroll
            for (int nt = 0; nt < 4; ++nt) {
                int n = wn * 32 + nt * 8 + g;
                bb[nt][0] = tf32r(Bs[kr * 72 + n]);
                bb[nt][1] = tf32r(Bs[(kr + 4) * 72 + n]);
            }
            #pragma unroll
            for (int mt = 0; mt < 2; ++mt)
                #pragma unroll
                for (int nt = 0; nt < 4; ++nt)
                    mma_tf32(acc[mt][nt], a[mt], bb[nt]);
        }
        __syncthreads();
    }

    #pragma unroll
    for (int mt = 0; mt < 2; ++mt) {
        const int row0 = m0 + wm * 32 + mt * 16 + g;
        #pragma unroll
        for (int nt = 0; nt < 4; ++nt) {
            const int col = n0 + wn * 32 + nt * 8 + tg * 2;
            #pragma unroll
            for (int h = 0; h < 2; ++h) {
                const int row = row0 + h * 8;
                float v0 = acc[mt][nt][h * 2 + 0] + res[(size_t)row * N + col];
                float v1 = acc[mt][nt][h * 2 + 1] + res[(size_t)row * N + col + 1];
                C[(size_t)row * N + col]     = v0;
                C[(size_t)row * N + col + 1] = v1;
            }
        }
    }
}

// ---------------------------------------------------------------------------
// FF1 (fp16): t = relu(h2 @ W1 + b1). K=128 fully smem-resident, one sync.
// BM=128, BN=64, 256 threads (8 warps: 4m x 2n, warp tile 32m x 32n).
// A: [128][136] half, B: [128][72] half ([k][n]).
// ---------------------------------------------------------------------------
#define F1_ASTR 136
#define F1_BOFF 17408                 // halfs (128*136)
#define F1_BSTR 72
#define F1_SMEM ((F1_BOFF + 128 * F1_BSTR) * 2)   // 53248 bytes

__global__ __launch_bounds__(256)
void ff1_kernel(const float* __restrict__ b1) {
    extern __shared__ __half smf[];
    __half* Ah = smf;
    __half* Bh = smf + F1_BOFF;
    const uint32_t smb = smem_u32(smf);

    const int m0 = blockIdx.x * 128;
    const int n0 = blockIdx.y * 64;
    const int tid = threadIdx.x, lane = tid & 31, warp = tid >> 5;
    const int wm = warp >> 1, wn = warp & 1;   // 4m x 2n
    const int g = lane >> 2, tg = lane & 3;
    const int lr = lane & 7, sel = lane >> 3;

    // load A (h2 half, full 128x128)
    #pragma unroll
    for (int i = 0; i < 8; i++) {
        int id = tid + i * 256;
        int m = id >> 4, c = (id & 15) << 3;
        cp16(Ah + m * F1_ASTR + c, g_h2h + (size_t)(m0 + m) * 128 + c);
    }
    // load B (W1 half slice, [k=128][n=64])
    #pragma unroll
    for (int i = 0; i < 4; i++) {
        int id = tid + i * 256;
        int k = id >> 3, c = (id & 7) << 3;
        cp16(Bh + k * F1_BSTR + c, g_W1h + (size_t)k * FFD + n0 + c);
    }
    cp_commit();
    cp_wait0();
    __syncthreads();

    uint32_t aoff[2];
    #pragma unroll
    for (int mt = 0; mt < 2; ++mt)
        aoff[mt] = (uint32_t)((wm * 32 + mt * 16 + (sel & 1) * 8 + lr) * F1_ASTR +
                              (sel >> 1) * 8);
    const uint32_t lm = (uint32_t)((lane & 15) * F1_BSTR + wn * 32 + ((lane >> 4) << 3));

    float acc[2][4][4];
    #pragma unroll
    for (int i = 0; i < 2; i++)
        #pragma unroll
        for (int j = 0; j < 4; j++)
            #pragma unroll
            for (int r = 0; r < 4; r++) acc[i][j][r] = 0.0f;

    #pragma unroll
    for (int kb = 0; kb < 128; kb += 16) {
        uint32_t a[2][4];
        #pragma unroll
        for (int mt = 0; mt < 2; ++mt)
            ldmx4(a[mt][0], a[mt][1], a[mt][2], a[mt][3],
                  smb + 2u * (aoff[mt] + kb));
        #pragma unroll
        for (int np = 0; np < 2; ++np) {
            uint32_t r0, r1, r2, r3;
            ldmx4t(r0, r1, r2, r3,
                   smb + 2u * (F1_BOFF + lm + kb * F1_BSTR + np * 16));
            uint32_t b0[2] = {r0, r1}, b1r[2] = {r2, r3};
            mma_f16(acc[0][np * 2],     a[0], b0);
            mma_f16(acc[1][np * 2],     a[1], b0);
            mma_f16(acc[0][np * 2 + 1], a[0], b1r);
            mma_f16(acc[1][np * 2 + 1], a[1], b1r);
        }
    }

    // epilogue: relu(+bias), write half
    #pragma unroll
    for (int mt = 0; mt < 2; ++mt) {
        #pragma unroll
        for (int nt = 0; nt < 4; ++nt) {
            const int col = n0 + wn * 32 + nt * 8 + tg * 2;
            const float bb0 = b1[col], bb1 = b1[col + 1];
            #pragma unroll
            for (int h = 0; h < 2; ++h) {
                const int row = m0 + wm * 32 + mt * 16 + g + h * 8;
                float v0 = fmaxf(acc[mt][nt][h * 2 + 0] + bb0, 0.0f);
                float v1 = fmaxf(acc[mt][nt][h * 2 + 1] + bb1, 0.0f);
                __half2 hv = __floats2half2_rn(v0, v1);
                *reinterpret_cast<uint32_t*>(g_th + (size_t)row * FFD + col) =
                    *reinterpret_cast<uint32_t*>(&hv);
            }
        }
    }
}

// ---------------------------------------------------------------------------
// FF2 (fp16): out = out1 + t @ W2 + b2. BM=128, BN=128, BK=64 double-buffered.
// 256 threads (8 warps: 4m x 2n, warp tile 32m x 64n).
// A: [128][72] half per stage; B: [64][136] half per stage.
// ---------------------------------------------------------------------------
#define F2_ASTR 72
#define F2_ABUF 9216                 // 128*72 halfs
#define F2_BSTR 136
#define F2_BBUF 8704                 // 64*136 halfs
#define F2_STAGE (F2_ABUF + F2_BBUF) // 17920 halfs
#define F2_SMEM (2 * F2_STAGE * 2)   // 71680 bytes

__global__ __launch_bounds__(256)
void ff2_kernel(const float* __restrict__ b2, const float* __restrict__ res,
                float* __restrict__ out) {
    extern __shared__ __half smf[];
    const uint32_t smb = smem_u32(smf);

    const int m0 = blockIdx.x * 128;
    const int tid = threadIdx.x, lane = tid & 31, warp = tid >> 5;
    const int wm = warp >> 1, wn = warp & 1;   // 4m x 2n; warp tile 32m x 64n
    const int g = lane >> 2, tg = lane & 3;
    const int lr = lane & 7, sel = lane >> 3;

    auto cpTile = [&](int stage, int k0) {
        __half* As = smf + stage * F2_STAGE;
        __half* Bs = As + F2_ABUF;
        #pragma unroll
        for (int i = 0; i < 4; i++) {
            int id = tid + i * 256;
            int m = id >> 3, c = (id & 7) << 3;
            cp16(As + m * F2_ASTR + c, g_th + (size_t)(m0 + m) * FFD + k0 + c);
        }
        #pragma unroll
        for (int i = 0; i < 4; i++) {
            int id = tid + i * 256;
            int k = id >> 4, c = (id & 15) << 3;
            cp16(Bs + k * F2_BSTR + c, g_W2h + (size_t)(k0 + k) * EDIM + c);
        }
    };

    uint32_t aoff[2];
    #pragma unroll
    for (int mt = 0; mt < 2; ++mt)
        aoff[mt] = (uint32_t)((wm * 32 + mt * 16 + (sel & 1) * 8 + lr) * F2_ASTR +
                              (sel >> 1) * 8);
    const uint32_t lm = (uint32_t)((lane & 15) * F2_BSTR + wn * 64 + ((lane >> 4) << 3));

    float acc[2][8][4];
    #pragma unroll
    for (int i = 0; i < 2; i++)
        #pragma unroll
        for (int j = 0; j < 8; j++)
            #pragma unroll
            for (int r = 0; r < 4; r++) acc[i][j][r] = 0.0f;

    cpTile(0, 0);
    cp_commit();

    for (int kt = 0; kt < 8; ++kt) {
        const int stage = kt & 1;
        if (kt + 1 < 8) { cpTile(stage ^ 1, (kt + 1) * 64); cp_commit(); cp_wait1(); }
        else            { cp_wait0(); }
        __syncthreads();
        const uint32_t abase = smb + 2u * (stage * F2_STAGE);
        const uint32_t bbase = smb + 2u * (stage * F2_STAGE + F2_ABUF + lm);
        #pragma unroll
        for (int ks = 0; ks < 4; ++ks) {
            const int kb = ks * 16;
            uint32_t a[2][4];
            #pragma unroll
            for (int mt = 0; mt < 2; ++mt)
                ldmx4(a[mt][0], a[mt][1], a[mt][2], a[mt][3],
                      abase + 2u * (aoff[mt] + kb));
            #pragma unroll
            for (int np = 0; np < 4; ++np) {
                uint32_t r0, r1, r2, r3;
                ldmx4t(r0, r1, r2, r3, bbase + 2u * (kb * F2_BSTR + np * 16));
                uint32_t b0[2] = {r0, r1}, b1r[2] = {r2, r3};
                mma_f16(acc[0][np * 2],     a[0], b0);
                mma_f16(acc[1][np * 2],     a[1], b0);
                mma_f16(acc[0][np * 2 + 1], a[0], b1r);
                mma_f16(acc[1][np * 2 + 1], a[1], b1r);
            }
        }
        __syncthreads();
    }

    #pragma unroll
    for (int mt = 0; mt < 2; ++mt) {
        #pragma unroll
        for (int nt = 0; nt < 8; ++nt) {
            const int col = wn * 64 + nt * 8 + tg * 2;
            const float bb0 = b2[col], bb1 = b2[col + 1];
            #pragma unroll
            for (int h = 0; h < 2; ++h) {
                const int row = m0 + wm * 32 + mt * 16 + g + h * 8;
                float v0 = acc[mt][nt][h * 2 + 0] + bb0 + res[(size_t)row * 128 + col];
                float v1 = acc[mt][nt][h * 2 + 1] + bb1 + res[(size_t)row * 128 + col + 1];
                out[(size_t)row * 128 + col]     = v0;
                out[(size_t)row * 128 + col + 1] = v1;
            }
        }
    }
}

// ---------------- launch ----------------
extern "C" void kernel_launch(void* const* d_in, const int* in_sizes, int n_in,
                              void* d_out, int out_size) {
    const float* x     = (const float*)d_in[0];
    const float* dis   = (const float*)d_in[1];
    const float* g_in  = (const float*)d_in[2];
    const float* g_po  = (const float*)d_in[3];
    const float* Wq    = (const float*)d_in[4];
    const float* Wk    = (const float*)d_in[5];
    const float* Wv    = (const float*)d_in[6];
    const float* alpha = (const float*)d_in[7];
    const float* Wo    = (const float*)d_in[8];
    const float* W1    = (const float*)d_in[9];
    const float* b1    = (const float*)d_in[10];
    const float* W2    = (const float*)d_in[11];
    const float* b2    = (const float*)d_in[12];
    float* out = (float*)d_out;

    float *p_h, *p_att, *p_out1;
    __half* p_h2h;
    cudaGetSymbolAddress((void**)&p_h,    g_h);
    cudaGetSymbolAddress((void**)&p_att,  g_att);
    cudaGetSymbolAddress((void**)&p_out1, g_out1);
    cudaGetSymbolAddress((void**)&p_h2h,  g_h2h);

    cudaFuncSetAttribute(big_kernel,
                         cudaFuncAttributeMaxDynamicSharedMemorySize, BIG_SMEM);
    cudaFuncSetAttribute(qkv_kernel,
                         cudaFuncAttributeMaxDynamicSharedMemorySize, QKV_SMEM);
    cudaFuncSetAttribute(wo_kernel,
                         cudaFuncAttributeMaxDynamicSharedMemorySize, SG_SMEM);
    cudaFuncSetAttribute(ff1_kernel,
                         cudaFuncAttributeMaxDynamicSharedMemorySize, F1_SMEM);
    cudaFuncSetAttribute(ff2_kernel,
                         cudaFuncAttributeMaxDynamicSharedMemorySize, F2_SMEM);

    pack_w_kernel<<<(EDIM * FFD + 255) / 256, 256>>>(W1, W2);
    rmsnorm_kernel<<<NTOK / 8, 256>>>(x, g_in, p_h);
    qkv_kernel<<<dim3(NTOK / 128, 4), 256, QKV_SMEM>>>(p_h, Wq, Wk, Wv);
    big_kernel<<<dim3(NSEQ / 128, NB), 512, BIG_SMEM>>>(dis, alpha);
    wo_kernel<<<dim3(NTOK / 128, 2), 256, SG_SMEM>>>(p_att, Wo, p_out1, x);
    rmsnorm_h_kernel<<<NTOK / 8, 256>>>(p_out1, g_po, p_h2h);
    ff1_kernel<<<dim3(NTOK / 128, 8), 256, F1_SMEM>>>(b1);
    ff2_kernel<<<NTOK / 128, 256, F2_SMEM>>>(b2, p_out1, out);
}